// round 17
// baseline (speedup 1.0000x reference)
#include <cuda_runtime.h>
#include <cuda_fp16.h>
#include <math.h>
#include <stdint.h>

#define BB 2
#define SS 2048
#define DD 1024
#define HH 16
#define HDIM 64
#define MM (BB*SS)

typedef __half f16;

// ---------------------------------------------------------------------------
// Scratch (__device__ globals; no runtime allocation)
// ---------------------------------------------------------------------------
__device__ f16 g_x16[MM*DD];
__device__ f16 g_wq16[DD*DD], g_wk16[DD*DD], g_wv16[DD*DD], g_wo16[DD*DD];
__device__ f16 g_q16[MM*DD], g_k16[MM*DD], g_v16[MM*DD], g_a16[MM*DD];
#define NMW (BB * SS * (SS / 32))
__device__ uint32_t g_pm[NMW];

// Host-side stream/event resources (created once at load time; streams and
// events are not device-memory allocations)
static cudaStream_t g_s1;
static cudaEvent_t g_evQ0, g_evO0;
namespace { struct StreamInit {
    StreamInit() {
        cudaStreamCreateWithFlags(&g_s1, cudaStreamNonBlocking);
        cudaEventCreateWithFlags(&g_evQ0, cudaEventDisableTiming);
        cudaEventCreateWithFlags(&g_evO0, cudaEventDisableTiming);
    }
} g_streamInit; }

// ---------------------------------------------------------------------------
// Helpers
// ---------------------------------------------------------------------------
__device__ __forceinline__ uint32_t pack_f16(f16 a, f16 b) {
    __half2 t = __halves2half2(a, b);
    return *reinterpret_cast<uint32_t*>(&t);
}

__device__ __forceinline__ float ex2(float x) {
    float r;
    asm("ex2.approx.ftz.f32 %0, %1;" : "=f"(r) : "f"(x));
    return r;
}

__device__ __forceinline__ void mma_f16(float* c, const uint32_t* a, const uint32_t* b) {
    asm volatile(
        "mma.sync.aligned.m16n8k16.row.col.f32.f16.f16.f32 "
        "{%0,%1,%2,%3}, {%4,%5,%6,%7}, {%8,%9}, {%0,%1,%2,%3};\n"
        : "+f"(c[0]), "+f"(c[1]), "+f"(c[2]), "+f"(c[3])
        : "r"(a[0]), "r"(a[1]), "r"(a[2]), "r"(a[3]), "r"(b[0]), "r"(b[1]));
}

__device__ __forceinline__ uint32_t smem_u32(const void* p) {
    return (uint32_t)__cvta_generic_to_shared(p);
}

#define CP16(sa, gp) \
    asm volatile("cp.async.cg.shared.global [%0], [%1], 16;\n" :: "r"(sa), "l"(gp))
#define CP_COMMIT() asm volatile("cp.async.commit_group;\n" ::: "memory")
template<int N>
__device__ __forceinline__ void cp_wait() {
    asm volatile("cp.async.wait_group %0;\n" :: "n"(N) : "memory");
}

#define LDMX4T(r0, r1, r2, r3, addr) \
    asm volatile("ldmatrix.sync.aligned.m8n8.x4.trans.shared.b16 {%0,%1,%2,%3}, [%4];\n" \
                 : "=r"(r0), "=r"(r1), "=r"(r2), "=r"(r3) : "r"(addr))
#define LDMX4(r0, r1, r2, r3, addr) \
    asm volatile("ldmatrix.sync.aligned.m8n8.x4.shared.b16 {%0,%1,%2,%3}, [%4];\n" \
                 : "=r"(r0), "=r"(r1), "=r"(r2), "=r"(r3) : "r"(addr))

// softmax in exp2 domain: 0.125 * log2(e), folded into q at qkv epilogue
#define SCL2 0.18033688011112042f

// ---------------------------------------------------------------------------
// Fused prep kernel: fp32->fp16 conversions + 1-bit mask pack
// ---------------------------------------------------------------------------
#define NX4 (MM * DD / 4)
#define NW4 (DD * DD / 4)
#define NSPLIT (NX4 + 4 * NW4)
#define NPREP (NSPLIT + NMW)

__global__ void prep_all(const float* __restrict__ x,
                         const float* __restrict__ wq, const float* __restrict__ wk,
                         const float* __restrict__ wv, const float* __restrict__ wo,
                         const int* __restrict__ mask,
                         f16* __restrict__ x16,
                         f16* __restrict__ wq16, f16* __restrict__ wk16,
                         f16* __restrict__ wv16, f16* __restrict__ wo16,
                         uint32_t* __restrict__ pm) {
    int i = blockIdx.x * blockDim.x + threadIdx.x;
    if (i >= NPREP) return;
    if (i < NSPLIT) {
        const float* s; f16* d; int off;
        if (i < NX4)                { s = x;  d = x16;  off = i; }
        else if (i < NX4 + NW4)     { s = wq; d = wq16; off = i - NX4; }
        else if (i < NX4 + 2 * NW4) { s = wk; d = wk16; off = i - NX4 - NW4; }
        else if (i < NX4 + 3 * NW4) { s = wv; d = wv16; off = i - NX4 - 2 * NW4; }
        else                        { s = wo; d = wo16; off = i - NX4 - 3 * NW4; }
        float4 v = ((const float4*)s)[off];
        uint2 u;
        u.x = pack_f16(__float2half_rn(v.x), __float2half_rn(v.y));
        u.y = pack_f16(__float2half_rn(v.z), __float2half_rn(v.w));
        ((uint2*)d)[off] = u;
    } else {
        int w = i - NSPLIT;
        const int4* src = (const int4*)(mask + (size_t)w * 32);
        uint32_t bits = 0;
        #pragma unroll
        for (int j = 0; j < 8; j++) {
            int4 m = src[j];
            bits |= (uint32_t)(m.x == 1) << (4 * j);
            bits |= (uint32_t)(m.y == 1) << (4 * j + 1);
            bits |= (uint32_t)(m.z == 1) << (4 * j + 2);
            bits |= (uint32_t)(m.w == 1) << (4 * j + 3);
        }
        pm[w] = bits;
    }
}

// ---------------------------------------------------------------------------
// fp16 single-pass GEMM: 128x128 CTA tile, 8 warps, 4-stage cp.async ring,
// ONE sync per chunk. m_off selects the M half (batch pipelining).
// ---------------------------------------------------------------------------
#define GKC 32
#define GPAD 40
#define GA_ELE (128 * GPAD)
#define GB_ELE (128 * GPAD)
#define G1STG (GA_ELE + GB_ELE)
#define G1O_WH GA_ELE
#define GNS 4
#define GEMM1_SMEM (GNS * G1STG * 2)

__device__ __forceinline__ void gemm1_issue(const f16* __restrict__ A,
                                            const f16* __restrict__ W,
                                            int m0, int n0, int kt,
                                            uint32_t sbase, int tid) {
    #pragma unroll
    for (int j = 0; j < 2; j++) {
        int cidx = tid + 256 * j;
        int row = cidx >> 2, col = (cidx & 3) * 8;
        uint32_t so = sbase + (row * GPAD + col) * 2;
        CP16(so, A + (size_t)(m0 + row) * DD + kt + col);
    }
    #pragma unroll
    for (int j = 0; j < 2; j++) {
        int cidx = tid + 256 * j;
        int row = cidx >> 2, col = (cidx & 3) * 8;
        uint32_t so = sbase + (G1O_WH + row * GPAD + col) * 2;
        CP16(so, W + (size_t)(n0 + row) * DD + kt + col);
    }
}

__device__ __forceinline__ void gemm1_main(const f16* __restrict__ A,
                                           const f16* __restrict__ W,
                                           int m0, int n0,
                                           float c[2][8][4]) {
    extern __shared__ f16 sm16[];
    const uint32_t sb = smem_u32(sm16);
    const int tid = threadIdx.x;
    const int wid = tid >> 5, lane = tid & 31;
    const int wm = (wid >> 1) * 32, wn = (wid & 1) * 64;
    const int a_lm = (lane & 15) * GPAD + (lane >> 4) * 8;
    const int b_lm = (wn + (lane >> 4) * 8 + (lane & 7)) * GPAD + ((lane >> 3) & 1) * 8;

    gemm1_issue(A, W, m0, n0, 0,       sb,                 tid); CP_COMMIT();
    gemm1_issue(A, W, m0, n0, GKC,     sb + G1STG * 2,     tid); CP_COMMIT();
    gemm1_issue(A, W, m0, n0, 2 * GKC, sb + 2 * G1STG * 2, tid); CP_COMMIT();

    const int NCH = DD / GKC;
    for (int ch = 0; ch < NCH; ch++) {
        cp_wait<2>();
        __syncthreads();
        if (ch + 3 < NCH) {
            gemm1_issue(A, W, m0, n0, (ch + 3) * GKC,
                        sb + ((ch + 3) % GNS) * G1STG * 2, tid);
            CP_COMMIT();
        }

        const uint32_t sA = sb + ((ch % GNS) * G1STG) * 2;

        #pragma unroll
        for (int ks = 0; ks < 2; ks++) {
            const int k0 = ks * 16;
            uint32_t ah[2][4];
            #pragma unroll
            for (int mt = 0; mt < 2; mt++) {
                uint32_t ad = sA + (uint32_t)((wm + mt * 16) * GPAD + a_lm + k0) * 2;
                LDMX4(ah[mt][0], ah[mt][1], ah[mt][2], ah[mt][3], ad);
            }
            #pragma unroll
            for (int j = 0; j < 4; j++) {
                uint32_t bd = sA + (uint32_t)(G1O_WH + 2 * j * 8 * GPAD + b_lm + k0) * 2;
                uint32_t bh[4];
                LDMX4(bh[0], bh[1], bh[2], bh[3], bd);
                #pragma unroll
                for (int sub = 0; sub < 2; sub++) {
                    const int nt = 2 * j + sub;
                    #pragma unroll
                    for (int mt = 0; mt < 2; mt++)
                        mma_f16(c[mt][nt], ah[mt], &bh[2 * sub]);
                }
            }
        }
    }
}

__global__ void __launch_bounds__(256, 2)
qkv_gemm(const f16* __restrict__ x16,
         const f16* __restrict__ wq16, const f16* __restrict__ wk16,
         const f16* __restrict__ wv16,
         f16* __restrict__ q16, f16* __restrict__ k16, f16* __restrict__ v16,
         int m_off) {
    const int z = blockIdx.z;
    const f16* Wh = (z == 0) ? wq16 : (z == 1) ? wk16 : wv16;
    f16* Y = (z == 0) ? q16 : (z == 1) ? k16 : v16;
    const int m0 = blockIdx.y * 128 + m_off, n0 = blockIdx.x * 128;
    const int tid = threadIdx.x;
    const int wid = tid >> 5, lane = tid & 31;
    const int g = lane >> 2, t = lane & 3;
    const int wm = (wid >> 1) * 32, wn = (wid & 1) * 64;

    float c[2][8][4] = {};
    gemm1_main(x16, Wh, m0, n0, c);

    const float qs = (z == 0) ? SCL2 : 1.0f;

    #pragma unroll
    for (int mt = 0; mt < 2; mt++) {
        const int r = m0 + wm + mt * 16 + g;
        #pragma unroll
        for (int nt = 0; nt < 8; nt++) {
            const int n = n0 + wn + nt * 8 + 2 * t;
            uint32_t u0 = pack_f16(__float2half_rn(c[mt][nt][0] * qs),
                                   __float2half_rn(c[mt][nt][1] * qs));
            uint32_t u1 = pack_f16(__float2half_rn(c[mt][nt][2] * qs),
                                   __float2half_rn(c[mt][nt][3] * qs));
            *(uint32_t*)&Y[(size_t)r * DD + n] = u0;
            *(uint32_t*)&Y[(size_t)(r + 8) * DD + n] = u1;
        }
    }
}

__global__ void __launch_bounds__(256, 2)
out_gemm(const f16* __restrict__ a16, const f16* __restrict__ wo16,
         const float* __restrict__ bo, float* __restrict__ out, int m_off) {
    const int m0 = blockIdx.y * 128 + m_off, n0 = blockIdx.x * 128;
    const int tid = threadIdx.x;
    const int wid = tid >> 5, lane = tid & 31;
    const int g = lane >> 2, t = lane & 3;
    const int wm = (wid >> 1) * 32, wn = (wid & 1) * 64;

    float c[2][8][4] = {};
    gemm1_main(a16, wo16, m0, n0, c);

    #pragma unroll
    for (int mt = 0; mt < 2; mt++) {
        const int r = m0 + wm + mt * 16 + g;
        #pragma unroll
        for (int nt = 0; nt < 8; nt++) {
            const int n = n0 + wn + nt * 8 + 2 * t;
            float bx = bo[n], by = bo[n + 1];
            float2 o0 = { c[mt][nt][0] + bx, c[mt][nt][1] + by };
            float2 o1 = { c[mt][nt][2] + bx, c[mt][nt][3] + by };
            *(float2*)&out[(size_t)r * DD + n] = o0;
            *(float2*)&out[(size_t)(r + 8) * DD + n] = o1;
        }
    }
}

// ---------------------------------------------------------------------------
// Flash attention: 64 q-rows/CTA, 4 warps x 16 rows, fp16 1-pass MMAs,
// no-max MUFU.EX2 softmax, 3-buffer KV ring (one sync/iter), packed mask,
// V via ldmatrix.x4.trans. b_off selects the batch (pipelining).
// ---------------------------------------------------------------------------
#define APAD 72
#define AT_ELE (64 * APAD)
#define AO_Q 0
#define AO_K(s) ((1 + 2 * (s)) * AT_ELE)
#define AO_V(s) ((2 + 2 * (s)) * AT_ELE)
#define ATTN_SMEM (7 * AT_ELE * 2)

__device__ __forceinline__ void attn_issue_kv(const f16* __restrict__ K16,
                                              const f16* __restrict__ V16,
                                              size_t brow, size_t hoff, int kt,
                                              uint32_t sb, int s, int tid) {
    #pragma unroll
    for (int j = 0; j < 4; j++) {
        int cidx = tid + 128 * j;
        int row = cidx >> 3, col = (cidx & 7) * 8;
        uint32_t so = sb + (AO_K(s) + row * APAD + col) * 2;
        size_t go = (brow + kt + row) * DD + hoff + col;
        CP16(so,              K16 + go);
        CP16(so + AT_ELE * 2, V16 + go);
    }
}

__global__ void __launch_bounds__(128, 3)
attn_kernel(const f16* __restrict__ Q16,
            const f16* __restrict__ K16, const f16* __restrict__ V16,
            const uint32_t* __restrict__ pm,
            f16* __restrict__ O16, int b_off)
{
    extern __shared__ f16 smA[];
    const uint32_t sb = smem_u32(smA);
    const int tid = threadIdx.x;
    const int wid = tid >> 5, lane = tid & 31;
    const int g = lane >> 2, t = lane & 3;
    const int q0 = blockIdx.x * 64;
    const int h = blockIdx.y;
    const int b = blockIdx.z + b_off;
    const int wm = wid * 16;

    const size_t hoff = (size_t)h * HDIM;
    const size_t brow = (size_t)b * SS;

    #pragma unroll
    for (int j = 0; j < 4; j++) {
        int cidx = tid + 128 * j;
        int row = cidx >> 3, col = (cidx & 7) * 8;
        uint32_t so = sb + (AO_Q + row * APAD + col) * 2;
        CP16(so, Q16 + (brow + q0 + row) * DD + hoff + col);
    }
    CP_COMMIT();
    attn_issue_kv(K16, V16, brow, hoff, 0,  sb, 0, tid); CP_COMMIT();
    attn_issue_kv(K16, V16, brow, hoff, 64, sb, 1, tid); CP_COMMIT();

    cp_wait<2>();
    __syncthreads();

    uint32_t aq[4][4];
    {
        const int a_lm = (lane & 15) * APAD + (lane >> 4) * 8;
        #pragma unroll
        for (int kk = 0; kk < 4; kk++) {
            uint32_t ad = sb + (uint32_t)(AO_Q + wm * APAD + a_lm + kk * 16) * 2;
            LDMX4(aq[kk][0], aq[kk][1], aq[kk][2], aq[kk][3], ad);
        }
    }

    float o[8][4] = {};
    float l0r = 0.f, l1r = 0.f;
    const int mrow0 = q0 + wm + g;
    const int NKT = SS / 64;

    const int k_lm = ((lane >> 4) * 8 + (lane & 7)) * APAD + ((lane >> 3) & 1) * 8;
    const int v_lm = (lane & 15) * APAD + (lane >> 4) * 8;
    const uint32_t* pr0 = pm + (brow + mrow0) * (SS / 32);
    const uint32_t* pr1 = pr0 + 8 * (SS / 32);
    const int s0 = 2 * t;

    for (int it = 0; it < NKT; it++) {
        uint2 w0 = *(const uint2*)(pr0 + it * 2);
        uint2 w1 = *(const uint2*)(pr1 + it * 2);

        cp_wait<1>();
        __syncthreads();
        if (it + 2 < NKT) {
            attn_issue_kv(K16, V16, brow, hoff, (it + 2) * 64,
                          sb, (it + 2) % 3, tid);
            CP_COMMIT();
        }

        const int buf = it % 3;
        const uint32_t kbase = sb + (uint32_t)AO_K(buf) * 2;
        const uint32_t vbase = sb + (uint32_t)(AO_V(buf) + v_lm) * 2;

        float cs[8][4] = {};
        #pragma unroll
        for (int kk = 0; kk < 4; kk++) {
            const int k0 = kk * 16;
            #pragma unroll
            for (int j = 0; j < 4; j++) {
                uint32_t kd = kbase + (uint32_t)(2 * j * 8 * APAD + k_lm + k0) * 2;
                uint32_t bh[4];
                LDMX4(bh[0], bh[1], bh[2], bh[3], kd);
                mma_f16(cs[2 * j],     aq[kk], &bh[0]);
                mma_f16(cs[2 * j + 1], aq[kk], &bh[2]);
            }
        }

        #pragma unroll
        for (int nt = 0; nt < 8; nt++) {
            const uint32_t wa = (nt < 4) ? w0.x : w0.y;
            const uint32_t wb = (nt < 4) ? w1.x : w1.y;
            const int p = 8 * (nt & 3) + s0;
            float e0 = ex2(cs[nt][0]);
            float e1 = ex2(cs[nt][1]);
            float e2 = ex2(cs[nt][2]);
            float e3 = ex2(cs[nt][3]);
            cs[nt][0] = ((wa >> p) & 1)       ? 0.f : e0;
            cs[nt][1] = ((wa >> (p + 1)) & 1) ? 0.f : e1;
            cs[nt][2] = ((wb >> p) & 1)       ? 0.f : e2;
            cs[nt][3] = ((wb >> (p + 1)) & 1) ? 0.f : e3;
            l0r += cs[nt][0] + cs[nt][1];
            l1r += cs[nt][2] + cs[nt][3];
        }

        #pragma unroll
        for (int kk = 0; kk < 4; kk++) {
            uint32_t ap[4];
            ap[0] = pack_f16(__float2half_rn(cs[2*kk][0]),   __float2half_rn(cs[2*kk][1]));
            ap[1] = pack_f16(__float2half_rn(cs[2*kk][2]),   __float2half_rn(cs[2*kk][3]));
            ap[2] = pack_f16(__float2half_rn(cs[2*kk+1][0]), __float2half_rn(cs[2*kk+1][1]));
            ap[3] = pack_f16(__float2half_rn(cs[2*kk+1][2]), __float2half_rn(cs[2*kk+1][3]));
            const uint32_t koff = kk * 16 * APAD * 2;
            #pragma unroll
            for (int np = 0; np < 4; np++) {
                uint32_t bh[4];
                LDMX4T(bh[0], bh[1], bh[2], bh[3], vbase + koff + np * 32);
                mma_f16(o[2 * np],     ap, &bh[0]);
                mma_f16(o[2 * np + 1], ap, &bh[2]);
            }
        }
    }

    l0r += __shfl_xor_sync(0xFFFFFFFF, l0r, 1);
    l0r += __shfl_xor_sync(0xFFFFFFFF, l0r, 2);
    l1r += __shfl_xor_sync(0xFFFFFFFF, l1r, 1);
    l1r += __shfl_xor_sync(0xFFFFFFFF, l1r, 2);

    float inv0 = 1.f / l0r, inv1 = 1.f / l1r;
    const size_t r0 = brow + q0 + wm + g;
    #pragma unroll
    for (int nt = 0; nt < 8; nt++) {
        const int n = nt * 8 + 2 * t;
        uint32_t u0 = pack_f16(__float2half_rn(o[nt][0] * inv0),
                               __float2half_rn(o[nt][1] * inv0));
        uint32_t u1 = pack_f16(__float2half_rn(o[nt][2] * inv1),
                               __float2half_rn(o[nt][3] * inv1));
        *(uint32_t*)&O16[r0 * DD + hoff + n] = u0;
        *(uint32_t*)&O16[(r0 + 8) * DD + hoff + n] = u1;
    }
}

// ---------------------------------------------------------------------------
extern "C" void kernel_launch(void* const* d_in, const int* in_sizes, int n_in,
                              void* d_out, int out_size)
{
    const float* x    = (const float*)d_in[0];
    const int*   mask = (const int*)  d_in[1];
    const float* Wq   = (const float*)d_in[2];
    const float* Wk   = (const float*)d_in[3];
    const float* Wv   = (const float*)d_in[4];
    const float* Wo   = (const float*)d_in[5];
    const float* bo   = (const float*)d_in[6];
    float* out = (float*)d_out;

    f16 *x16, *wq16, *wk16, *wv16, *wo16;
    f16 *q16, *k16, *v16, *a16;
    uint32_t* pmp;
    cudaGetSymbolAddress((void**)&x16, g_x16);
    cudaGetSymbolAddress((void**)&wq16, g_wq16); cudaGetSymbolAddress((void**)&wk16, g_wk16);
    cudaGetSymbolAddress((void**)&wv16, g_wv16); cudaGetSymbolAddress((void**)&wo16, g_wo16);
    cudaGetSymbolAddress((void**)&q16, g_q16);   cudaGetSymbolAddress((void**)&k16, g_k16);
    cudaGetSymbolAddress((void**)&v16, g_v16);   cudaGetSymbolAddress((void**)&a16, g_a16);
    cudaGetSymbolAddress((void**)&pmp, g_pm);

    cudaFuncSetAttribute(qkv_gemm, cudaFuncAttributeMaxDynamicSharedMemorySize, GEMM1_SMEM);
    cudaFuncSetAttribute(out_gemm, cudaFuncAttributeMaxDynamicSharedMemorySize, GEMM1_SMEM);
    cudaFuncSetAttribute(attn_kernel, cudaFuncAttributeMaxDynamicSharedMemorySize, ATTN_SMEM);

    const int HM = MM / 2;   // 2048 rows per batch half
    dim3 gqh(DD / 128, HM / 128, 3);
    dim3 gah(SS / 64, HH, 1);
    dim3 goh(DD / 128, HM / 128);

    // stream0 (capture stream): prep -> qkv_b0 -> qkv_b1 -> attn_b1 -> out_b1
    // stream1 (forked):                      attn_b0 -> out_b0
    prep_all<<<(NPREP + 255) / 256, 256>>>(x, Wq, Wk, Wv, Wo, mask,
                                           x16, wq16, wk16, wv16, wo16, pmp);

    qkv_gemm<<<gqh, 256, GEMM1_SMEM>>>(x16, wq16, wk16, wv16,
                                       q16, k16, v16, 0);
    cudaEventRecord(g_evQ0, 0);

    qkv_gemm<<<gqh, 256, GEMM1_SMEM>>>(x16, wq16, wk16, wv16,
                                       q16, k16, v16, HM);

    // fork: batch-0 attention + projection on stream1
    cudaStreamWaitEvent(g_s1, g_evQ0, 0);
    attn_kernel<<<gah, 128, ATTN_SMEM, g_s1>>>(q16, k16, v16, pmp, a16, 0);
    out_gemm<<<goh, 256, GEMM1_SMEM, g_s1>>>(a16, wo16, bo, out, 0);
    cudaEventRecord(g_evO0, g_s1);

    // stream0: batch-1 attention + projection (after qkv_b1, stream order)
    attn_kernel<<<gah, 128, ATTN_SMEM>>>(q16, k16, v16, pmp, a16, 1);
    out_gemm<<<goh, 256, GEMM1_SMEM>>>(a16, wo16, bo, out, HM);

    // join stream1 back into the capture stream
    cudaStreamWaitEvent(0, g_evO0, 0);
}